// round 3
// baseline (speedup 1.0000x reference)
#include <cuda_runtime.h>
#include <math.h>
#include <stdint.h>

// Problem constants
#define B_   2
#define P_   4000
#define NP_  4096
#define D_   64
#define M_   512
#define HW_  214272           // 496*432
#define TP   64               // pillars per block
#define TN   128              // src rows per tile

// Output layout (concatenated, element offsets)
#define SPP_OFF  ((size_t)54853632)    // B*128*HW
#define SSC_OFF  ((size_t)109707264)   // 2*B*128*HW
#define PP_OFF   ((size_t)137134080)   // + B*64*HW
#define PM_OFF   ((size_t)137646080)   // + B*P*64
#define DENSE_ELEMS ((size_t)137134080)

// Scratch: per-pixel winning pillar (last-writer-wins = max p)
__device__ int g_winner[B_ * HW_];

// ---------------- f32x2 packed-math helpers ----------------
__device__ __forceinline__ unsigned long long pack2(float x) {
    unsigned long long r;
    asm("mov.b64 %0, {%1, %1};" : "=l"(r) : "f"(x));
    return r;
}
__device__ __forceinline__ unsigned long long fma2(unsigned long long a,
                                                   unsigned long long b,
                                                   unsigned long long c) {
    unsigned long long d;
    asm("fma.rn.f32x2 %0, %1, %2, %3;" : "=l"(d) : "l"(a), "l"(b), "l"(c));
    return d;
}
__device__ __forceinline__ float2 unpack2(unsigned long long v) {
    float2 f;
    asm("mov.b64 {%0, %1}, %2;" : "=f"(f.x), "=f"(f.y) : "l"(v));
    return f;
}

// Sorted-ascending top-8 insert; tv[0] is the current min (gatekeeper).
// Strict compares preserve lax.top_k tie-breaking (lower index wins) because
// each thread's index stream is increasing.
__device__ __forceinline__ void tryInsert(float (&tv)[8], int (&ti)[8], float v, int x) {
    if (v > tv[0]) {
        tv[0] = v; ti[0] = x;
#pragma unroll
        for (int j = 0; j < 7; ++j) {
            if (tv[j] > tv[j + 1]) {
                float tf = tv[j]; tv[j] = tv[j + 1]; tv[j + 1] = tf;
                int   tx = ti[j]; ti[j] = ti[j + 1]; ti[j + 1] = tx;
            }
        }
    }
}

// ---------------- winner kernels ----------------
__global__ void winner_init_kernel() {
    int i = blockIdx.x * blockDim.x + threadIdx.x;
    if (i < B_ * HW_) g_winner[i] = -1;
}

__global__ void winner_build_kernel(const int* __restrict__ idx) {
    int t = blockIdx.x * blockDim.x + threadIdx.x;
    if (t < B_ * P_) {
        int b = t / P_;
        atomicMax(&g_winner[b * HW_ + idx[t]], t - b * P_);
    }
}

// ---------------- fused GEMM + top-8 + softmax-aggregate ----------------
// Computes, for each pillar p in its 64-pillar tile:
//   logits[n] = dot(pillar[p], src[srcbase + n]),  n in [0, ntiles*128)
//   top-8 (value desc, index-asc ties), softmax over the 8, weighted sum of
//   the 8 src rows -> outPos[(b*P + p)*64 + :].
// srcPerBatch = NP_ for points, 0 for the shared memory matrix W.
extern "C" __global__ void __launch_bounds__(256, 1)
topk_agg_kernel(const float* __restrict__ pillars,
                const float* __restrict__ src,
                float* __restrict__ outPos,
                int srcPerBatch, int ntiles)
{
    extern __shared__ char smraw[];
    float* pS = (float*)smraw;            // phase A: [64][64]  (k-major pillar tile)
    float* nS = pS + TP * D_;             // phase A: [64][128] (k-major src tile)
    float* candV = (float*)smraw;         // phase B: [64][129] (padded rows)
    int*   candI = (int*)(smraw + 33024);
    float* wV    = (float*)(smraw + 66048);  // [64][8]
    int*   wI    = (int*)(smraw + 68096);    // [64][8]

    const int tid = threadIdx.x;
    const int b   = blockIdx.y;
    const int pt0 = blockIdx.x * TP;
    const int pg  = tid & 15;   // pillar group: pillars 4*pg .. 4*pg+3
    const int ng  = tid >> 4;   // src-col group: cols 8*ng .. 8*ng+7
    const int srcbase = b * srcPerBatch;

    // Load pillar tile transposed: pS[k][p]; zero-pad past P_.
    for (int i = tid; i < TP * D_; i += 256) {
        int p = i >> 6, k = i & 63;
        float v = 0.f;
        if (pt0 + p < P_) v = pillars[((size_t)b * P_ + pt0 + p) * D_ + k];
        pS[k * TP + p] = v;
    }

    float tv[4][8]; int ti[4][8];
#pragma unroll
    for (int i = 0; i < 4; ++i)
#pragma unroll
        for (int s = 0; s < 8; ++s) { tv[i][s] = -1e30f; ti[i][s] = 0; }

#pragma unroll 1
    for (int t = 0; t < ntiles; ++t) {
        __syncthreads();
        // Stage src tile transposed into nS[k][n] (conflict-free scalar stores,
        // consecutive lanes -> consecutive n).
        const float4* s4 = (const float4*)(src + (size_t)(srcbase + t * TN) * D_);
#pragma unroll
        for (int j = 0; j < 8; ++j) {
            int li = tid + j * 256;
            int n = li & 127, kq = li >> 7;
            float4 v = s4[n * 16 + kq];
            nS[(kq * 4 + 0) * TN + n] = v.x;
            nS[(kq * 4 + 1) * TN + n] = v.y;
            nS[(kq * 4 + 2) * TN + n] = v.z;
            nS[(kq * 4 + 3) * TN + n] = v.w;
        }
        __syncthreads();

        unsigned long long acc[4][4];
#pragma unroll
        for (int i = 0; i < 4; ++i)
#pragma unroll
            for (int j = 0; j < 4; ++j) acc[i][j] = 0ull;

#pragma unroll 4
        for (int k = 0; k < D_; ++k) {
            float4 pa = *(const float4*)(pS + k * TP + 4 * pg);
            ulonglong2 na = *(const ulonglong2*)(nS + k * TN + 8 * ng);
            ulonglong2 nb = *(const ulonglong2*)(nS + k * TN + 8 * ng + 4);
            unsigned long long pk0 = pack2(pa.x), pk1 = pack2(pa.y),
                               pk2 = pack2(pa.z), pk3 = pack2(pa.w);
            acc[0][0] = fma2(pk0, na.x, acc[0][0]);
            acc[0][1] = fma2(pk0, na.y, acc[0][1]);
            acc[0][2] = fma2(pk0, nb.x, acc[0][2]);
            acc[0][3] = fma2(pk0, nb.y, acc[0][3]);
            acc[1][0] = fma2(pk1, na.x, acc[1][0]);
            acc[1][1] = fma2(pk1, na.y, acc[1][1]);
            acc[1][2] = fma2(pk1, nb.x, acc[1][2]);
            acc[1][3] = fma2(pk1, nb.y, acc[1][3]);
            acc[2][0] = fma2(pk2, na.x, acc[2][0]);
            acc[2][1] = fma2(pk2, na.y, acc[2][1]);
            acc[2][2] = fma2(pk2, nb.x, acc[2][2]);
            acc[2][3] = fma2(pk2, nb.y, acc[2][3]);
            acc[3][0] = fma2(pk3, na.x, acc[3][0]);
            acc[3][1] = fma2(pk3, na.y, acc[3][1]);
            acc[3][2] = fma2(pk3, nb.x, acc[3][2]);
            acc[3][3] = fma2(pk3, nb.y, acc[3][3]);
        }

        int nb0 = t * TN + 8 * ng;
#pragma unroll
        for (int i = 0; i < 4; ++i) {
#pragma unroll
            for (int j = 0; j < 4; ++j) {
                float2 v = unpack2(acc[i][j]);
                tryInsert(tv[i], ti[i], v.x, nb0 + 2 * j);
                tryInsert(tv[i], ti[i], v.y, nb0 + 2 * j + 1);
            }
        }
    }

    __syncthreads();  // all threads done reading pS/nS before aliasing as candV

    // Dump per-thread candidates: 16 threads x 8 per pillar = 128.
#pragma unroll
    for (int i = 0; i < 4; ++i) {
        int row = 4 * pg + i;
#pragma unroll
        for (int s = 0; s < 8; ++s) {
            candV[row * 129 + ng * 8 + s] = tv[i][s];
            candI[row * 129 + ng * 8 + s] = ti[i][s];
        }
    }
    __syncthreads();

    // One thread per pillar: select global top-8 of 128 candidates, softmax.
    if (tid < TP && pt0 + tid < P_) {
        float* cv = candV + tid * 129;
        int*   ci = candI + tid * 129;
        float selV[8]; int selI[8];
#pragma unroll 1
        for (int s = 0; s < 8; ++s) {
            float bv = -2e30f; int bi = 0x7fffffff; int bpos = 0;
            for (int j = 0; j < 128; ++j) {
                float v = cv[j]; int x = ci[j];
                if (v > bv || (v == bv && x < bi)) { bv = v; bi = x; bpos = j; }
            }
            cv[bpos] = -3e30f;
            selV[s] = bv; selI[s] = bi;
        }
        float m = selV[0], sum = 0.f, w[8];
#pragma unroll
        for (int s = 0; s < 8; ++s) { w[s] = expf(selV[s] - m); sum += w[s]; }
        float inv = 1.f / sum;
#pragma unroll
        for (int s = 0; s < 8; ++s) { wV[tid * 8 + s] = w[s] * inv; wI[tid * 8 + s] = selI[s]; }
    }
    __syncthreads();

    // 4 threads per pillar: weighted gather of the 8 selected src rows.
    {
        int pl = tid >> 2, part = tid & 3;
        if (pt0 + pl < P_) {
            float a[16];
#pragma unroll
            for (int j = 0; j < 16; ++j) a[j] = 0.f;
#pragma unroll
            for (int s = 0; s < 8; ++s) {
                float w = wV[pl * 8 + s];
                int gi = wI[pl * 8 + s];
                const float4* q = (const float4*)(src + (size_t)(srcbase + gi) * D_ + part * 16);
                float4 q0 = q[0], q1 = q[1], q2 = q[2], q3 = q[3];
                a[0]  += w * q0.x; a[1]  += w * q0.y; a[2]  += w * q0.z; a[3]  += w * q0.w;
                a[4]  += w * q1.x; a[5]  += w * q1.y; a[6]  += w * q1.z; a[7]  += w * q1.w;
                a[8]  += w * q2.x; a[9]  += w * q2.y; a[10] += w * q2.z; a[11] += w * q2.w;
                a[12] += w * q3.x; a[13] += w * q3.y; a[14] += w * q3.z; a[15] += w * q3.w;
            }
            float4* o = (float4*)(outPos + ((size_t)b * P_ + pt0 + pl) * D_ + part * 16);
            o[0] = make_float4(a[0],  a[1],  a[2],  a[3]);
            o[1] = make_float4(a[4],  a[5],  a[6],  a[7]);
            o[2] = make_float4(a[8],  a[9],  a[10], a[11]);
            o[3] = make_float4(a[12], a[13], a[14], a[15]);
        }
    }
}

// ---------------- dense scatter (winner pillars only) ----------------
__global__ void scatter_kernel(const float* __restrict__ pillars,
                               const float* __restrict__ scale,
                               const int* __restrict__ indices,
                               float* __restrict__ out)
{
    int t = blockIdx.x * blockDim.x + threadIdx.x;  // B*P*4
    if (t >= B_ * P_ * 4) return;
    int part = t & 3;
    int pp = t >> 2;
    int b = pp / P_, p = pp - b * P_;
    int pix = indices[pp];
    if (g_winner[b * HW_ + pix] != p) return;

    size_t cb  = (size_t)b * 128 * HW_;
    size_t cbs = (size_t)b * 64 * HW_;
    const float* pil  = pillars + (size_t)pp * D_ + part * 16;
    const float* sc   = scale   + (size_t)pp * D_ + part * 16;
    const float* posP = out + PP_OFF + (size_t)pp * D_ + part * 16;
    const float* posM = out + PM_OFF + (size_t)pp * D_ + part * 16;

#pragma unroll
    for (int j = 0; j < 16; ++j) {
        int c = part * 16 + j;
        float pv = pil[j], pmv = posM[j], ppv = posP[j], scv = sc[j];
        out[cb + (size_t)c * HW_ + pix]                    = pv;   // sp low
        out[cb + (size_t)(64 + c) * HW_ + pix]             = pmv;  // sp high
        out[SPP_OFF + cb + (size_t)c * HW_ + pix]          = pv;   // sp_point low
        out[SPP_OFF + cb + (size_t)(64 + c) * HW_ + pix]   = ppv;  // sp_point high
        out[SSC_OFF + cbs + (size_t)c * HW_ + pix]         = scv;  // sp_scale
    }
}

// ---------------- launch ----------------
extern "C" void kernel_launch(void* const* d_in, const int* in_sizes, int n_in,
                              void* d_out, int out_size) {
    const float* pillars = (const float*)d_in[0];   // [B,P,64]
    const float* scale   = (const float*)d_in[1];   // [B,P,64]
    const float* points  = (const float*)d_in[2];   // [B,NP,64]
    const float* W       = (const float*)d_in[3];   // [512,64]
    const int*   indices = (const int*)d_in[4];     // [B,P]
    float* out = (float*)d_out;

    const int SMEM_BYTES = 70144;
    cudaFuncSetAttribute(topk_agg_kernel,
                         cudaFuncAttributeMaxDynamicSharedMemorySize, SMEM_BYTES);

    // 1) zero the dense BEV outputs (pos_point/pos_mem are fully overwritten)
    cudaMemsetAsync(d_out, 0, DENSE_ELEMS * sizeof(float), 0);

    // 2) winner resolution (last duplicate index wins = max p)
    winner_init_kernel<<<(B_ * HW_ + 255) / 256, 256>>>();
    winner_build_kernel<<<(B_ * P_ + 255) / 256, 256>>>(indices);

    // 3) point attention: top-8 of points.pillars^T + softmax aggregate
    dim3 grid((P_ + TP - 1) / TP, B_);  // (63, 2)
    topk_agg_kernel<<<grid, 256, SMEM_BYTES>>>(pillars, points, out + PP_OFF,
                                               NP_, NP_ / TN);

    // 4) memory attention: top-8 of pillars.W^T + softmax aggregate
    topk_agg_kernel<<<grid, 256, SMEM_BYTES>>>(pillars, W, out + PM_OFF,
                                               0, M_ / TN);

    // 5) scatter winner columns into the dense grids
    scatter_kernel<<<(B_ * P_ * 4 + 255) / 256, 256>>>(pillars, scale, indices, out);
}

// round 4
// speedup vs baseline: 1.1221x; 1.1221x over previous
#include <cuda_runtime.h>
#include <math.h>
#include <stdint.h>

// Problem constants
#define B_   2
#define P_   4000
#define NP_  4096
#define D_   64
#define M_   512
#define HW_  214272           // 496*432
#define TP   64               // pillars per block
#define TN   128              // src rows per tile

// Output layout (concatenated, element offsets)
#define SPP_OFF  ((size_t)54853632)    // B*128*HW
#define SSC_OFF  ((size_t)109707264)   // 2*B*128*HW
#define PP_OFF   ((size_t)137134080)   // + B*64*HW
#define PM_OFF   ((size_t)137646080)   // + B*P*64
#define DENSE_ELEMS ((size_t)137134080)

// Fused-kernel block partition
#define TOPK_BLOCKS 126                // 63 pillar tiles x 2 batches
#define ZBLK        2048               // zero-fill blocks
#define F4_TOTAL    (DENSE_ELEMS / 4)  // 34283520 float4, divides ZBLK exactly
#define F4_PER_BLK  (F4_TOTAL / ZBLK)  // 16740

// Scratch: per-pixel winning pillar (last-writer-wins = max p)
__device__ int g_winner[B_ * HW_];

// ---------------- f32x2 packed-math helpers ----------------
__device__ __forceinline__ unsigned long long pack2(float x) {
    unsigned long long r;
    asm("mov.b64 %0, {%1, %1};" : "=l"(r) : "f"(x));
    return r;
}
__device__ __forceinline__ unsigned long long fma2(unsigned long long a,
                                                   unsigned long long b,
                                                   unsigned long long c) {
    unsigned long long d;
    asm("fma.rn.f32x2 %0, %1, %2, %3;" : "=l"(d) : "l"(a), "l"(b), "l"(c));
    return d;
}
__device__ __forceinline__ float2 unpack2(unsigned long long v) {
    float2 f;
    asm("mov.b64 {%0, %1}, %2;" : "=f"(f.x), "=f"(f.y) : "l"(v));
    return f;
}

// Sorted-ascending top-8 insert; tv[0] is the current min (gatekeeper).
__device__ __forceinline__ void tryInsert(float (&tv)[8], int (&ti)[8], float v, int x) {
    if (v > tv[0]) {
        tv[0] = v; ti[0] = x;
#pragma unroll
        for (int j = 0; j < 7; ++j) {
            if (tv[j] > tv[j + 1]) {
                float tf = tv[j]; tv[j] = tv[j + 1]; tv[j + 1] = tf;
                int   tx = ti[j]; ti[j] = ti[j + 1]; ti[j + 1] = tx;
            }
        }
    }
}

// ---------------- winner kernels ----------------
__global__ void winner_init_kernel() {
    int i = blockIdx.x * blockDim.x + threadIdx.x;
    if (i < B_ * HW_) g_winner[i] = -1;
}

__global__ void winner_build_kernel(const int* __restrict__ idx) {
    int t = blockIdx.x * blockDim.x + threadIdx.x;
    if (t < B_ * P_) {
        int b = t / P_;
        atomicMax(&g_winner[b * HW_ + idx[t]], t - b * P_);
    }
}

// ---------------- fused GEMM + top-8 + softmax-aggregate (device fn) -------
// For each pillar p in the 64-pillar tile:
//   logits[n] = dot(pillar[p], src[srcbase + n]),  n in [0, ntiles*128)
//   top-8 (value desc, index-asc ties), softmax over the 8, weighted sum of
//   the 8 src rows -> outPos[(b*P + p)*64 + :].
__device__ __forceinline__ void topk_phase(
    const float* __restrict__ pillars,
    const float* __restrict__ src,
    float* __restrict__ outPos,
    int srcPerBatch, int ntiles,
    int b, int pt0, char* smraw)
{
    float* pS = (float*)smraw;            // phase A: [64][64]  (k-major pillar tile)
    float* nS = pS + TP * D_;             // phase A: [64][128] (k-major src tile)
    float* candV = (float*)smraw;         // phase B: [64][129] (padded rows)
    int*   candI = (int*)(smraw + 33024);
    float* wV    = (float*)(smraw + 66048);  // [64][8]
    int*   wI    = (int*)(smraw + 68096);    // [64][8]

    const int tid = threadIdx.x;
    const int pg  = tid & 15;   // pillar group: pillars 4*pg .. 4*pg+3
    const int ng  = tid >> 4;   // src-col group: cols 8*ng .. 8*ng+7
    const int srcbase = b * srcPerBatch;

    // Load pillar tile transposed: pS[k][p]; zero-pad past P_.
    for (int i = tid; i < TP * D_; i += 256) {
        int p = i >> 6, k = i & 63;
        float v = 0.f;
        if (pt0 + p < P_) v = pillars[((size_t)b * P_ + pt0 + p) * D_ + k];
        pS[k * TP + p] = v;
    }

    float tv[4][8]; int ti[4][8];
#pragma unroll
    for (int i = 0; i < 4; ++i)
#pragma unroll
        for (int s = 0; s < 8; ++s) { tv[i][s] = -1e30f; ti[i][s] = 0; }

#pragma unroll 1
    for (int t = 0; t < ntiles; ++t) {
        __syncthreads();
        const float4* s4 = (const float4*)(src + (size_t)(srcbase + t * TN) * D_);
#pragma unroll
        for (int j = 0; j < 8; ++j) {
            int li = tid + j * 256;
            int n = li & 127, kq = li >> 7;
            float4 v = s4[n * 16 + kq];
            nS[(kq * 4 + 0) * TN + n] = v.x;
            nS[(kq * 4 + 1) * TN + n] = v.y;
            nS[(kq * 4 + 2) * TN + n] = v.z;
            nS[(kq * 4 + 3) * TN + n] = v.w;
        }
        __syncthreads();

        unsigned long long acc[4][4];
#pragma unroll
        for (int i = 0; i < 4; ++i)
#pragma unroll
            for (int j = 0; j < 4; ++j) acc[i][j] = 0ull;

#pragma unroll 4
        for (int k = 0; k < D_; ++k) {
            float4 pa = *(const float4*)(pS + k * TP + 4 * pg);
            ulonglong2 na = *(const ulonglong2*)(nS + k * TN + 8 * ng);
            ulonglong2 nb = *(const ulonglong2*)(nS + k * TN + 8 * ng + 4);
            unsigned long long pk0 = pack2(pa.x), pk1 = pack2(pa.y),
                               pk2 = pack2(pa.z), pk3 = pack2(pa.w);
            acc[0][0] = fma2(pk0, na.x, acc[0][0]);
            acc[0][1] = fma2(pk0, na.y, acc[0][1]);
            acc[0][2] = fma2(pk0, nb.x, acc[0][2]);
            acc[0][3] = fma2(pk0, nb.y, acc[0][3]);
            acc[1][0] = fma2(pk1, na.x, acc[1][0]);
            acc[1][1] = fma2(pk1, na.y, acc[1][1]);
            acc[1][2] = fma2(pk1, nb.x, acc[1][2]);
            acc[1][3] = fma2(pk1, nb.y, acc[1][3]);
            acc[2][0] = fma2(pk2, na.x, acc[2][0]);
            acc[2][1] = fma2(pk2, na.y, acc[2][1]);
            acc[2][2] = fma2(pk2, nb.x, acc[2][2]);
            acc[2][3] = fma2(pk2, nb.y, acc[2][3]);
            acc[3][0] = fma2(pk3, na.x, acc[3][0]);
            acc[3][1] = fma2(pk3, na.y, acc[3][1]);
            acc[3][2] = fma2(pk3, nb.x, acc[3][2]);
            acc[3][3] = fma2(pk3, nb.y, acc[3][3]);
        }

        int nb0 = t * TN + 8 * ng;
#pragma unroll
        for (int i = 0; i < 4; ++i) {
#pragma unroll
            for (int j = 0; j < 4; ++j) {
                float2 v = unpack2(acc[i][j]);
                tryInsert(tv[i], ti[i], v.x, nb0 + 2 * j);
                tryInsert(tv[i], ti[i], v.y, nb0 + 2 * j + 1);
            }
        }
    }

    __syncthreads();  // done reading pS/nS before aliasing as candV

    // Dump per-thread candidates: 16 threads x 8 per pillar = 128.
#pragma unroll
    for (int i = 0; i < 4; ++i) {
        int row = 4 * pg + i;
#pragma unroll
        for (int s = 0; s < 8; ++s) {
            candV[row * 129 + ng * 8 + s] = tv[i][s];
            candI[row * 129 + ng * 8 + s] = ti[i][s];
        }
    }
    __syncthreads();

    // One thread per pillar: select global top-8 of 128 candidates, softmax.
    if (tid < TP && pt0 + tid < P_) {
        float* cv = candV + tid * 129;
        int*   ci = candI + tid * 129;
        float selV[8]; int selI[8];
#pragma unroll 1
        for (int s = 0; s < 8; ++s) {
            float bv = -2e30f; int bi = 0x7fffffff; int bpos = 0;
            for (int j = 0; j < 128; ++j) {
                float v = cv[j]; int x = ci[j];
                if (v > bv || (v == bv && x < bi)) { bv = v; bi = x; bpos = j; }
            }
            cv[bpos] = -3e30f;
            selV[s] = bv; selI[s] = bi;
        }
        float m = selV[0], sum = 0.f, w[8];
#pragma unroll
        for (int s = 0; s < 8; ++s) { w[s] = expf(selV[s] - m); sum += w[s]; }
        float inv = 1.f / sum;
#pragma unroll
        for (int s = 0; s < 8; ++s) { wV[tid * 8 + s] = w[s] * inv; wI[tid * 8 + s] = selI[s]; }
    }
    __syncthreads();

    // 4 threads per pillar: weighted gather of the 8 selected src rows.
    {
        int pl = tid >> 2, part = tid & 3;
        if (pt0 + pl < P_) {
            float a[16];
#pragma unroll
            for (int j = 0; j < 16; ++j) a[j] = 0.f;
#pragma unroll
            for (int s = 0; s < 8; ++s) {
                float w = wV[pl * 8 + s];
                int gi = wI[pl * 8 + s];
                const float4* q = (const float4*)(src + (size_t)(srcbase + gi) * D_ + part * 16);
                float4 q0 = q[0], q1 = q[1], q2 = q[2], q3 = q[3];
                a[0]  += w * q0.x; a[1]  += w * q0.y; a[2]  += w * q0.z; a[3]  += w * q0.w;
                a[4]  += w * q1.x; a[5]  += w * q1.y; a[6]  += w * q1.z; a[7]  += w * q1.w;
                a[8]  += w * q2.x; a[9]  += w * q2.y; a[10] += w * q2.z; a[11] += w * q2.w;
                a[12] += w * q3.x; a[13] += w * q3.y; a[14] += w * q3.z; a[15] += w * q3.w;
            }
            float4* o = (float4*)(outPos + ((size_t)b * P_ + pt0 + pl) * D_ + part * 16);
            o[0] = make_float4(a[0],  a[1],  a[2],  a[3]);
            o[1] = make_float4(a[4],  a[5],  a[6],  a[7]);
            o[2] = make_float4(a[8],  a[9],  a[10], a[11]);
            o[3] = make_float4(a[12], a[13], a[14], a[15]);
        }
    }
    __syncthreads();  // smem reuse safe for a following phase
}

// ---------------- fused kernel: topk blocks + zero-fill blocks -------------
// Blocks [0, TOPK_BLOCKS): point attention then memory attention for one
// 64-pillar tile. Blocks [TOPK_BLOCKS, TOPK_BLOCKS+ZBLK): zero a contiguous
// 262 KB chunk of the dense BEV outputs with STG.128 streaming stores.
// Compute blocks occupy wave 1; zero blocks backfill idle SMs, overlapping
// the DRAM-write-bound fill with the fma-bound GEMM.
extern "C" __global__ void __launch_bounds__(256, 1)
fused_kernel(const float* __restrict__ pillars,
             const float* __restrict__ points,
             const float* __restrict__ W,
             float* __restrict__ out)
{
    extern __shared__ char smraw[];
    int bid = blockIdx.x;

    if (bid >= TOPK_BLOCKS) {
        // ---- zero-fill block ----
        size_t base = (size_t)(bid - TOPK_BLOCKS) * F4_PER_BLK;
        float4* o = (float4*)out + base;
        float4 z = make_float4(0.f, 0.f, 0.f, 0.f);
        for (int i = threadIdx.x; i < F4_PER_BLK; i += 256) {
            __stcs(o + i, z);   // evict-first: don't thrash L2 for compute blocks
        }
        return;
    }

    // ---- top-k attention block ----
    int b   = bid / 63;
    int pt0 = (bid - b * 63) * TP;

    // point attention -> point_positive_features
    topk_phase(pillars, points, out + PP_OFF, NP_, NP_ / TN, b, pt0, smraw);
    // memory attention -> memory_positive_features
    topk_phase(pillars, W, out + PM_OFF, 0, M_ / TN, b, pt0, smraw);
}

// ---------------- dense scatter (winner pillars only) ----------------
__global__ void scatter_kernel(const float* __restrict__ pillars,
                               const float* __restrict__ scale,
                               const int* __restrict__ indices,
                               float* __restrict__ out)
{
    int t = blockIdx.x * blockDim.x + threadIdx.x;  // B*P*4
    if (t >= B_ * P_ * 4) return;
    int part = t & 3;
    int pp = t >> 2;
    int b = pp / P_, p = pp - b * P_;
    int pix = indices[pp];
    if (g_winner[b * HW_ + pix] != p) return;

    size_t cb  = (size_t)b * 128 * HW_;
    size_t cbs = (size_t)b * 64 * HW_;
    const float* pil  = pillars + (size_t)pp * D_ + part * 16;
    const float* sc   = scale   + (size_t)pp * D_ + part * 16;
    const float* posP = out + PP_OFF + (size_t)pp * D_ + part * 16;
    const float* posM = out + PM_OFF + (size_t)pp * D_ + part * 16;

#pragma unroll
    for (int j = 0; j < 16; ++j) {
        int c = part * 16 + j;
        float pv = pil[j], pmv = posM[j], ppv = posP[j], scv = sc[j];
        out[cb + (size_t)c * HW_ + pix]                    = pv;   // sp low
        out[cb + (size_t)(64 + c) * HW_ + pix]             = pmv;  // sp high
        out[SPP_OFF + cb + (size_t)c * HW_ + pix]          = pv;   // sp_point low
        out[SPP_OFF + cb + (size_t)(64 + c) * HW_ + pix]   = ppv;  // sp_point high
        out[SSC_OFF + cbs + (size_t)c * HW_ + pix]         = scv;  // sp_scale
    }
}

// ---------------- launch ----------------
extern "C" void kernel_launch(void* const* d_in, const int* in_sizes, int n_in,
                              void* d_out, int out_size) {
    const float* pillars = (const float*)d_in[0];   // [B,P,64]
    const float* scale   = (const float*)d_in[1];   // [B,P,64]
    const float* points  = (const float*)d_in[2];   // [B,NP,64]
    const float* W       = (const float*)d_in[3];   // [512,64]
    const int*   indices = (const int*)d_in[4];     // [B,P]
    float* out = (float*)d_out;

    const int SMEM_BYTES = 70144;
    cudaFuncSetAttribute(fused_kernel,
                         cudaFuncAttributeMaxDynamicSharedMemorySize, SMEM_BYTES);

    // 1) winner resolution (last duplicate index wins = max p)
    winner_init_kernel<<<(B_ * HW_ + 255) / 256, 256>>>();
    winner_build_kernel<<<(B_ * P_ + 255) / 256, 256>>>(indices);

    // 2) fused: zero-fill of dense outputs overlapped with both attention
    //    passes (point + memory top-8, softmax, aggregate)
    fused_kernel<<<TOPK_BLOCKS + ZBLK, 256, SMEM_BYTES>>>(pillars, points, W, out);

    // 3) scatter winner columns into the dense grids
    scatter_kernel<<<(B_ * P_ * 4 + 255) / 256, 256>>>(pillars, scale, indices, out);
}

// round 5
// speedup vs baseline: 1.1547x; 1.0290x over previous
#include <cuda_runtime.h>
#include <math.h>
#include <stdint.h>

// Problem constants
#define B_   2
#define P_   4000
#define NP_  4096
#define D_   64
#define M_   512
#define HW_  214272           // 496*432
#define TP   64               // pillars per block
#define TN   128              // src rows per tile

// Output layout (concatenated, element offsets)
#define SPP_OFF  ((size_t)54853632)    // B*128*HW
#define SSC_OFF  ((size_t)109707264)   // 2*B*128*HW
#define PP_OFF   ((size_t)137134080)   // + B*64*HW
#define PM_OFF   ((size_t)137646080)   // + B*P*64
#define DENSE_ELEMS ((size_t)137134080)

// Fused-kernel block partition
#define TOPK_BLOCKS 126                // 63 pillar tiles x 2 batches
#define ZBLK        2048               // zero-fill blocks
#define F4_TOTAL    (DENSE_ELEMS / 4)  // 34283520 float4, divides ZBLK exactly
#define F4_PER_BLK  (F4_TOTAL / ZBLK)  // 16740

// Scratch: per-pixel winning pillar (last-writer-wins = max p)
__device__ int g_winner[B_ * HW_];

// ---------------- f32x2 packed-math helpers ----------------
__device__ __forceinline__ unsigned long long pack2(float x) {
    unsigned long long r;
    asm("mov.b64 %0, {%1, %1};" : "=l"(r) : "f"(x));
    return r;
}
__device__ __forceinline__ unsigned long long fma2(unsigned long long a,
                                                   unsigned long long b,
                                                   unsigned long long c) {
    unsigned long long d;
    asm("fma.rn.f32x2 %0, %1, %2, %3;" : "=l"(d) : "l"(a), "l"(b), "l"(c));
    return d;
}
__device__ __forceinline__ float2 unpack2(unsigned long long v) {
    float2 f;
    asm("mov.b64 {%0, %1}, %2;" : "=f"(f.x), "=f"(f.y) : "l"(v));
    return f;
}

// Sorted-ascending top-8 insert; tv[0] is the current min (gatekeeper).
__device__ __forceinline__ void tryInsert(float (&tv)[8], int (&ti)[8], float v, int x) {
    if (v > tv[0]) {
        tv[0] = v; ti[0] = x;
#pragma unroll
        for (int j = 0; j < 7; ++j) {
            if (tv[j] > tv[j + 1]) {
                float tf = tv[j]; tv[j] = tv[j + 1]; tv[j + 1] = tf;
                int   tx = ti[j]; ti[j] = ti[j + 1]; ti[j + 1] = tx;
            }
        }
    }
}

// ---------------- winner kernels ----------------
__global__ void winner_init_kernel() {
    int i = blockIdx.x * blockDim.x + threadIdx.x;
    if (i < B_ * HW_) g_winner[i] = -1;
}

__global__ void winner_build_kernel(const int* __restrict__ idx) {
    int t = blockIdx.x * blockDim.x + threadIdx.x;
    if (t < B_ * P_) {
        int b = t / P_;
        atomicMax(&g_winner[b * HW_ + idx[t]], t - b * P_);
    }
}

// ---------------- fused GEMM + top-8 + softmax-aggregate (device fn) -------
__device__ __forceinline__ void topk_phase(
    const float* __restrict__ pillars,
    const float* __restrict__ src,
    float* __restrict__ outPos,
    int srcPerBatch, int ntiles,
    int b, int pt0, char* smraw)
{
    float* pS = (float*)smraw;            // phase A: [64][64]  (k-major pillar tile)
    float* nS = pS + TP * D_;             // phase A: [64][128] (k-major src tile)
    float* candV = (float*)smraw;         // phase B: [64][129] (padded rows)
    int*   candI = (int*)(smraw + 33024);
    float* wV    = (float*)(smraw + 66048);  // [64][8]
    int*   wI    = (int*)(smraw + 68096);    // [64][8]

    const int tid = threadIdx.x;
    const int pg  = tid & 15;   // pillar group: pillars 4*pg .. 4*pg+3
    const int ng  = tid >> 4;   // src-col group: cols 8*ng .. 8*ng+7
    const int srcbase = b * srcPerBatch;

    // Load pillar tile transposed: pS[k][p]; zero-pad past P_.
    for (int i = tid; i < TP * D_; i += 256) {
        int p = i >> 6, k = i & 63;
        float v = 0.f;
        if (pt0 + p < P_) v = pillars[((size_t)b * P_ + pt0 + p) * D_ + k];
        pS[k * TP + p] = v;
    }

    float tv[4][8]; int ti[4][8];
#pragma unroll
    for (int i = 0; i < 4; ++i)
#pragma unroll
        for (int s = 0; s < 8; ++s) { tv[i][s] = -1e30f; ti[i][s] = 0; }

#pragma unroll 1
    for (int t = 0; t < ntiles; ++t) {
        __syncthreads();
        const float4* s4 = (const float4*)(src + (size_t)(srcbase + t * TN) * D_);
#pragma unroll
        for (int j = 0; j < 8; ++j) {
            int li = tid + j * 256;
            int n = li & 127, kq = li >> 7;
            float4 v = s4[n * 16 + kq];
            nS[(kq * 4 + 0) * TN + n] = v.x;
            nS[(kq * 4 + 1) * TN + n] = v.y;
            nS[(kq * 4 + 2) * TN + n] = v.z;
            nS[(kq * 4 + 3) * TN + n] = v.w;
        }
        __syncthreads();

        unsigned long long acc[4][4];
#pragma unroll
        for (int i = 0; i < 4; ++i)
#pragma unroll
            for (int j = 0; j < 4; ++j) acc[i][j] = 0ull;

#pragma unroll 4
        for (int k = 0; k < D_; ++k) {
            float4 pa = *(const float4*)(pS + k * TP + 4 * pg);
            ulonglong2 na = *(const ulonglong2*)(nS + k * TN + 8 * ng);
            ulonglong2 nb = *(const ulonglong2*)(nS + k * TN + 8 * ng + 4);
            unsigned long long pk0 = pack2(pa.x), pk1 = pack2(pa.y),
                               pk2 = pack2(pa.z), pk3 = pack2(pa.w);
            acc[0][0] = fma2(pk0, na.x, acc[0][0]);
            acc[0][1] = fma2(pk0, na.y, acc[0][1]);
            acc[0][2] = fma2(pk0, nb.x, acc[0][2]);
            acc[0][3] = fma2(pk0, nb.y, acc[0][3]);
            acc[1][0] = fma2(pk1, na.x, acc[1][0]);
            acc[1][1] = fma2(pk1, na.y, acc[1][1]);
            acc[1][2] = fma2(pk1, nb.x, acc[1][2]);
            acc[1][3] = fma2(pk1, nb.y, acc[1][3]);
            acc[2][0] = fma2(pk2, na.x, acc[2][0]);
            acc[2][1] = fma2(pk2, na.y, acc[2][1]);
            acc[2][2] = fma2(pk2, nb.x, acc[2][2]);
            acc[2][3] = fma2(pk2, nb.y, acc[2][3]);
            acc[3][0] = fma2(pk3, na.x, acc[3][0]);
            acc[3][1] = fma2(pk3, na.y, acc[3][1]);
            acc[3][2] = fma2(pk3, nb.x, acc[3][2]);
            acc[3][3] = fma2(pk3, nb.y, acc[3][3]);
        }

        int nb0 = t * TN + 8 * ng;
#pragma unroll
        for (int i = 0; i < 4; ++i) {
#pragma unroll
            for (int j = 0; j < 4; ++j) {
                float2 v = unpack2(acc[i][j]);
                tryInsert(tv[i], ti[i], v.x, nb0 + 2 * j);
                tryInsert(tv[i], ti[i], v.y, nb0 + 2 * j + 1);
            }
        }
    }

    __syncthreads();  // done reading pS/nS before aliasing as candV

    // Dump per-thread candidates: 16 threads x 8 per pillar = 128.
#pragma unroll
    for (int i = 0; i < 4; ++i) {
        int row = 4 * pg + i;
#pragma unroll
        for (int s = 0; s < 8; ++s) {
            candV[row * 129 + ng * 8 + s] = tv[i][s];
            candI[row * 129 + ng * 8 + s] = ti[i][s];
        }
    }
    __syncthreads();

    // One thread per pillar: select global top-8 of 128 candidates, softmax.
    if (tid < TP && pt0 + tid < P_) {
        float* cv = candV + tid * 129;
        int*   ci = candI + tid * 129;
        float selV[8]; int selI[8];
#pragma unroll 1
        for (int s = 0; s < 8; ++s) {
            float bv = -2e30f; int bi = 0x7fffffff; int bpos = 0;
            for (int j = 0; j < 128; ++j) {
                float v = cv[j]; int x = ci[j];
                if (v > bv || (v == bv && x < bi)) { bv = v; bi = x; bpos = j; }
            }
            cv[bpos] = -3e30f;
            selV[s] = bv; selI[s] = bi;
        }
        float m = selV[0], sum = 0.f, w[8];
#pragma unroll
        for (int s = 0; s < 8; ++s) { w[s] = expf(selV[s] - m); sum += w[s]; }
        float inv = 1.f / sum;
#pragma unroll
        for (int s = 0; s < 8; ++s) { wV[tid * 8 + s] = w[s] * inv; wI[tid * 8 + s] = selI[s]; }
    }
    __syncthreads();

    // 4 threads per pillar: weighted gather of the 8 selected src rows.
    {
        int pl = tid >> 2, part = tid & 3;
        if (pt0 + pl < P_) {
            float a[16];
#pragma unroll
            for (int j = 0; j < 16; ++j) a[j] = 0.f;
#pragma unroll
            for (int s = 0; s < 8; ++s) {
                float w = wV[pl * 8 + s];
                int gi = wI[pl * 8 + s];
                const float4* q = (const float4*)(src + (size_t)(srcbase + gi) * D_ + part * 16);
                float4 q0 = q[0], q1 = q[1], q2 = q[2], q3 = q[3];
                a[0]  += w * q0.x; a[1]  += w * q0.y; a[2]  += w * q0.z; a[3]  += w * q0.w;
                a[4]  += w * q1.x; a[5]  += w * q1.y; a[6]  += w * q1.z; a[7]  += w * q1.w;
                a[8]  += w * q2.x; a[9]  += w * q2.y; a[10] += w * q2.z; a[11] += w * q2.w;
                a[12] += w * q3.x; a[13] += w * q3.y; a[14] += w * q3.z; a[15] += w * q3.w;
            }
            float4* o = (float4*)(outPos + ((size_t)b * P_ + pt0 + pl) * D_ + part * 16);
            o[0] = make_float4(a[0],  a[1],  a[2],  a[3]);
            o[1] = make_float4(a[4],  a[5],  a[6],  a[7]);
            o[2] = make_float4(a[8],  a[9],  a[10], a[11]);
            o[3] = make_float4(a[12], a[13], a[14], a[15]);
        }
    }
    __syncthreads();  // smem reuse safe for a following phase
}

// ---------------- fused kernel: topk blocks + zero-fill blocks -------------
// Fill blocks use write-through (__stwt) STG.128: hypothesis is that the
// ~1.85 TB/s fill ceiling seen with both cudaMemset and __stcs is the L2
// dirty-line allocate+writeback drain; .wt skips dirty allocation.
extern "C" __global__ void __launch_bounds__(256, 1)
fused_kernel(const float* __restrict__ pillars,
             const float* __restrict__ points,
             const float* __restrict__ W,
             float* __restrict__ out)
{
    extern __shared__ char smraw[];
    int bid = blockIdx.x;

    if (bid >= TOPK_BLOCKS) {
        // ---- zero-fill block (write-through streaming stores) ----
        size_t base = (size_t)(bid - TOPK_BLOCKS) * F4_PER_BLK;
        float4* o = (float4*)out + base;
        float4 z = make_float4(0.f, 0.f, 0.f, 0.f);
#pragma unroll 4
        for (int i = threadIdx.x; i < F4_PER_BLK; i += 256) {
            __stwt(o + i, z);
        }
        return;
    }

    // ---- top-k attention block ----
    int b   = bid / 63;
    int pt0 = (bid - b * 63) * TP;

    // point attention -> point_positive_features
    topk_phase(pillars, points, out + PP_OFF, NP_, NP_ / TN, b, pt0, smraw);
    // memory attention -> memory_positive_features
    topk_phase(pillars, W, out + PM_OFF, 0, M_ / TN, b, pt0, smraw);
}

// ---------------- dense scatter (winner pillars only) ----------------
// One thread per (pillar, channel): 512k threads -> latency-hiding via
// parallelism instead of per-thread ILP (R4 version was 85us at occ=10%,
// issue=0.3% with only 32k threads).
__global__ void __launch_bounds__(256)
scatter_kernel(const float* __restrict__ pillars,
               const float* __restrict__ scale,
               const int* __restrict__ indices,
               float* __restrict__ out)
{
    int t = blockIdx.x * blockDim.x + threadIdx.x;  // B*P*64
    if (t >= B_ * P_ * D_) return;
    int c  = t & 63;
    int pp = t >> 6;
    int b  = pp / P_, p = pp - b * P_;
    int pix = __ldg(&indices[pp]);
    if (g_winner[b * HW_ + pix] != p) return;   // last-duplicate-wins

    float pv  = pillars[(size_t)pp * D_ + c];
    float scv = scale[(size_t)pp * D_ + c];
    float ppv = out[PP_OFF + (size_t)pp * D_ + c];
    float pmv = out[PM_OFF + (size_t)pp * D_ + c];

    size_t cb  = (size_t)b * 128 * HW_;
    size_t cbs = (size_t)b * 64 * HW_;
    out[cb + (size_t)c * HW_ + pix]                  = pv;   // sp low
    out[cb + (size_t)(64 + c) * HW_ + pix]           = pmv;  // sp high
    out[SPP_OFF + cb + (size_t)c * HW_ + pix]        = pv;   // sp_point low
    out[SPP_OFF + cb + (size_t)(64 + c) * HW_ + pix] = ppv;  // sp_point high
    out[SSC_OFF + cbs + (size_t)c * HW_ + pix]       = scv;  // sp_scale
}

// ---------------- launch ----------------
extern "C" void kernel_launch(void* const* d_in, const int* in_sizes, int n_in,
                              void* d_out, int out_size) {
    const float* pillars = (const float*)d_in[0];   // [B,P,64]
    const float* scale   = (const float*)d_in[1];   // [B,P,64]
    const float* points  = (const float*)d_in[2];   // [B,NP,64]
    const float* W       = (const float*)d_in[3];   // [512,64]
    const int*   indices = (const int*)d_in[4];     // [B,P]
    float* out = (float*)d_out;

    const int SMEM_BYTES = 70144;
    cudaFuncSetAttribute(fused_kernel,
                         cudaFuncAttributeMaxDynamicSharedMemorySize, SMEM_BYTES);

    // 1) winner resolution (last duplicate index wins = max p)
    winner_init_kernel<<<(B_ * HW_ + 255) / 256, 256>>>();
    winner_build_kernel<<<(B_ * P_ + 255) / 256, 256>>>(indices);

    // 2) fused: zero-fill of dense outputs overlapped with both attention
    //    passes (point + memory top-8, softmax, aggregate)
    fused_kernel<<<TOPK_BLOCKS + ZBLK, 256, SMEM_BYTES>>>(pillars, points, W, out);

    // 3) scatter winner columns into the dense grids
    scatter_kernel<<<(B_ * P_ * D_ + 255) / 256, 256>>>(pillars, scale, indices, out);
}